// round 1
// baseline (speedup 1.0000x reference)
#include <cuda_runtime.h>

#define DIM     256
#define NTREES  512
#define TDEPTH  6
#define UNITS   16
#define LEAVES  64
#define BATCH   1024

#define BT      128                 // batch rows per block
#define NT      8                   // trees per block (one per warp)
#define KC      32                  // k-chunk
#define XPAD    35                  // x_s row stride (3l mod 32 -> conflict-free)
#define SELW    (NT * TDEPTH)       // 48
#define NBLK    (NTREES / NT)       // 64
#define BBLK    (BATCH / BT)        // 8
#define OPAD    17                  // out_s row stride

#define SMEM_FLOATS (BT*XPAD + KC*SELW + NT*UNITS*LEAVES + BT*OPAD)  // 16384
#define SMEM_BYTES  (SMEM_FLOATS * 4)                                // 65536

__device__ float g_sel[DIM * NTREES * TDEPTH];          // 3 MB
__device__ float g_partial[NBLK * BATCH * UNITS];       // 4 MB

// ---------------------------------------------------------------------------
// Kernel 1: sparsemax along last axis (size 6) of feature_selection_logits.
// One thread per (i, n) row. Matches jax reference exactly (count-of-support).
// ---------------------------------------------------------------------------
__global__ void sparsemax6_kernel(const float* __restrict__ fsl) {
    int row = blockIdx.x * blockDim.x + threadIdx.x;
    if (row >= DIM * NTREES) return;
    const float* zp = fsl + (size_t)row * TDEPTH;
    float v[TDEPTH], s[TDEPTH];
#pragma unroll
    for (int j = 0; j < TDEPTH; j++) { v[j] = zp[j]; s[j] = v[j]; }
    // bubble sort descending (fully unrolled, stays in registers)
#pragma unroll
    for (int a = 0; a < TDEPTH - 1; a++)
#pragma unroll
        for (int b = 0; b < TDEPTH - 1 - a; b++)
            if (s[b] < s[b + 1]) { float t = s[b]; s[b] = s[b + 1]; s[b + 1] = t; }

    float cs[TDEPTH];
    float acc = 0.f;
    int cnt = 0;
#pragma unroll
    for (int j = 0; j < TDEPTH; j++) {
        acc += s[j];
        cs[j] = acc;
        if (s[j] * (float)(j + 1) > acc - 1.f) cnt++;
    }
    float csk = cs[0];
#pragma unroll
    for (int j = 1; j < TDEPTH; j++) if (cnt == j + 1) csk = cs[j];
    float tau = (csk - 1.f) / (float)cnt;

    float* op = g_sel + (size_t)row * TDEPTH;
#pragma unroll
    for (int j = 0; j < TDEPTH; j++) op[j] = fmaxf(v[j] - tau, 0.f);
}

// ---------------------------------------------------------------------------
// Kernel 2: fused fv-GEMM + gates + leaf products + response contraction,
// reduced over the block's 8 trees into a per-(n-block) partial.
// Block: 256 threads = 8 warps. Warp w handles tree n0+w (all sel/response
// shared-memory reads are warp-uniform broadcasts). Lane l handles batch rows
// r*32+l for r=0..3 (x_s reads conflict-free via XPAD=35).
// ---------------------------------------------------------------------------
__global__ __launch_bounds__(256, 2)
void node_kernel(const float* __restrict__ x,
                 const float* __restrict__ th,
                 const float* __restrict__ lt,
                 const float* __restrict__ resp) {
    extern __shared__ float sm[];
    float* x_s    = sm;                               // BT * XPAD
    float* sel_s  = x_s + BT * XPAD;                  // KC * SELW
    float* resp_s = sel_s + KC * SELW;                // NT * UNITS * LEAVES
    float* out_s  = resp_s + NT * UNITS * LEAVES;     // BT * OPAD

    const int tid  = threadIdx.x;
    const int w    = tid >> 5;
    const int l    = tid & 31;
    const int nblk = blockIdx.x;
    const int bblk = blockIdx.y;
    const int n0   = nblk * NT;
    const int b0   = bblk * BT;

    // Load response tile for the 8 trees (8192 floats, float4-vectorized).
    {
        const float4* rg = (const float4*)(resp + (size_t)n0 * UNITS * LEAVES);
        for (int i = tid; i < NT * UNITS * LEAVES / 4; i += 256)
            ((float4*)resp_s)[i] = rg[i];
    }
    // Zero the block-local output accumulator.
    for (int i = tid; i < BT * OPAD; i += 256) out_s[i] = 0.f;

    // Per-warp tree parameters (uniform across the warp).
    float thv[TDEPTH], einv[TDEPTH];
#pragma unroll
    for (int d = 0; d < TDEPTH; d++) {
        thv[d]  = th[(n0 + w) * TDEPTH + d];
        einv[d] = __expf(-lt[(n0 + w) * TDEPTH + d]);
    }

    float fv[4][TDEPTH];
#pragma unroll
    for (int r = 0; r < 4; r++)
#pragma unroll
        for (int d = 0; d < TDEPTH; d++) fv[r][d] = 0.f;

    // --- GEMM mainloop: fv[b, tree, d] = sum_k x[b,k] * sel[k, tree, d] ---
    for (int k0 = 0; k0 < DIM; k0 += KC) {
        __syncthreads();
        // x tile: BT x KC (coalesced float4 loads, conflict-free scalar stores)
        for (int i = tid; i < BT * KC / 4; i += 256) {
            int b  = i >> 3;   // KC/4 = 8 float4 per row
            int kq = i & 7;
            float4 vx = *(const float4*)(x + (size_t)(b0 + b) * DIM + k0 + kq * 4);
            float* dst = x_s + b * XPAD + kq * 4;
            dst[0] = vx.x; dst[1] = vx.y; dst[2] = vx.z; dst[3] = vx.w;
        }
        // sel tile: KC x 48 (48 contiguous floats per k-row in global)
        for (int i = tid; i < KC * SELW / 4; i += 256) {
            int k  = i / 12;
            int c4 = i % 12;
            float4 vs = *(const float4*)(g_sel + (size_t)(k0 + k) * (NTREES * TDEPTH)
                                         + n0 * TDEPTH + c4 * 4);
            float* dst = sel_s + k * SELW + c4 * 4;
            dst[0] = vs.x; dst[1] = vs.y; dst[2] = vs.z; dst[3] = vs.w;
        }
        __syncthreads();

#pragma unroll 8
        for (int k = 0; k < KC; k++) {
            float xr[4];
#pragma unroll
            for (int r = 0; r < 4; r++) xr[r] = x_s[(r * 32 + l) * XPAD + k];
            const float* sp = sel_s + k * SELW + w * TDEPTH;   // warp-uniform
#pragma unroll
            for (int d = 0; d < TDEPTH; d++) {
                float sv = sp[d];
#pragma unroll
                for (int r = 0; r < 4; r++) fv[r][d] = fmaf(xr[r], sv, fv[r][d]);
            }
        }
    }

    // --- Epilogue: gates -> leaf weights -> response dot -> tree reduce ---
    const float4* rp = (const float4*)(resp_s + w * (UNITS * LEAVES));
#pragma unroll
    for (int r = 0; r < 4; r++) {
        float gp[TDEPTH], gn[TDEPTH];
#pragma unroll
        for (int d = 0; d < TDEPTH; d++) {
            float t = (fv[r][d] - thv[d]) * einv[d];
            float g = __saturatef(0.5f * t + 0.5f);   // gate for bit==0 branch
            gp[d] = g;
            gn[d] = 1.f - g;                          // gate for bit==1 branch
        }
        // Leaf weight factorization: w[c] = wlo[c&3] * whi[c>>2]
        float wlo[4];
        wlo[0] = gp[0] * gp[1];
        wlo[1] = gn[0] * gp[1];
        wlo[2] = gp[0] * gn[1];
        wlo[3] = gn[0] * gn[1];
        float a2[2] = { gp[2], gn[2] };
        float a3[4], a4[8], whi[16];
#pragma unroll
        for (int j = 0; j < 2; j++) { a3[j] = a2[j] * gp[3]; a3[j + 2] = a2[j] * gn[3]; }
#pragma unroll
        for (int j = 0; j < 4; j++) { a4[j] = a3[j] * gp[4]; a4[j + 4] = a3[j] * gn[4]; }
#pragma unroll
        for (int j = 0; j < 8; j++) { whi[j] = a4[j] * gp[5]; whi[j + 8] = a4[j] * gn[5]; }

        float oacc[UNITS];
#pragma unroll
        for (int u = 0; u < UNITS; u++) oacc[u] = 0.f;
#pragma unroll 4
        for (int hi = 0; hi < 16; hi++) {
            float wh = whi[hi];
            float w0 = wlo[0] * wh, w1 = wlo[1] * wh;
            float w2 = wlo[2] * wh, w3 = wlo[3] * wh;
#pragma unroll
            for (int u = 0; u < UNITS; u++) {
                float4 rv = rp[u * 16 + hi];          // warp-uniform LDS.128
                oacc[u] += w0 * rv.x + w1 * rv.y + w2 * rv.z + w3 * rv.w;
            }
        }
        int row = r * 32 + l;
#pragma unroll
        for (int u = 0; u < UNITS; u++)
            atomicAdd(out_s + row * OPAD + u, oacc[u]);   // conflict-free lanes
    }

    __syncthreads();
    // Write the block's tree-summed partial for (nblk, b0..b0+127, u).
    for (int i = tid; i < BT * UNITS; i += 256) {
        int b = i >> 4, u = i & 15;
        g_partial[((size_t)nblk * BATCH + b0 + b) * UNITS + u] = out_s[b * OPAD + u];
    }
}

// ---------------------------------------------------------------------------
// Kernel 3: reduce the 64 n-block partials and apply mean over trees.
// ---------------------------------------------------------------------------
__global__ void reduce_kernel(float* __restrict__ out) {
    int i = blockIdx.x * blockDim.x + threadIdx.x;   // 0 .. 16383
    float acc = 0.f;
#pragma unroll 8
    for (int nb = 0; nb < NBLK; nb++)
        acc += g_partial[(size_t)nb * BATCH * UNITS + i];
    out[i] = acc * (1.f / (float)NTREES);
}

// ---------------------------------------------------------------------------
extern "C" void kernel_launch(void* const* d_in, const int* in_sizes, int n_in,
                              void* d_out, int out_size) {
    const float* x    = (const float*)d_in[0];   // (1024, 256)
    const float* fsl  = (const float*)d_in[1];   // (256, 512, 6)
    const float* th   = (const float*)d_in[2];   // (512, 6)
    const float* lt   = (const float*)d_in[3];   // (512, 6)
    const float* resp = (const float*)d_in[4];   // (512, 16, 64)
    float* out = (float*)d_out;                  // (1024, 16)

    cudaFuncSetAttribute(node_kernel,
                         cudaFuncAttributeMaxDynamicSharedMemorySize, SMEM_BYTES);

    sparsemax6_kernel<<<(DIM * NTREES + 255) / 256, 256>>>(fsl);
    dim3 grid(NBLK, BBLK);
    node_kernel<<<grid, 256, SMEM_BYTES>>>(x, th, lt, resp);
    reduce_kernel<<<BATCH * UNITS / 256, 256>>>(out);
}